// round 2
// baseline (speedup 1.0000x reference)
#include <cuda_runtime.h>
#include <cstdint>

// Problem constants
#define S_   1024
#define B_   2
#define D_   1024
#define H_   16
#define DH_  64
#define L_   4
#define WIN_ 64
#define M_   (S_*B_)   // 2048 token rows

// ---------------- scratch (no allocations allowed) ----------------
__device__ float g_mod[L_*B_*6*D_];   // adaLN modulation, all layers
__device__ float g_xm [M_*D_];        // LN-modulated activations
__device__ float g_qkv[M_*3*D_];      // qkv projections
__device__ float g_o  [M_*D_];        // attention output (pre out-proj)
__device__ float g_h  [M_*4*D_];      // MLP hidden

// ---------------- adaLN modulation: mod = relu(c) @ wada^T + bada ----------------
// one warp per (layer l, output j); both batch rows per weight read
__global__ void mod_kernel(const float* __restrict__ c,
                           const float* __restrict__ wada,
                           const float* __restrict__ bada) {
    int tid  = threadIdx.x;
    int lane = tid & 31;
    int widx = blockIdx.x * 8 + (tid >> 5);       // 0 .. L*6D-1
    int l = widx / (6 * D_);
    int j = widx % (6 * D_);
    const float* wr = wada + ((size_t)l * 6 * D_ + j) * D_;
    float a0 = 0.f, a1 = 0.f;
    for (int k = lane; k < D_; k += 32) {
        float wv = wr[k];
        a0 += wv * fmaxf(c[k], 0.f);
        a1 += wv * fmaxf(c[D_ + k], 0.f);
    }
    #pragma unroll
    for (int off = 16; off; off >>= 1) {
        a0 += __shfl_xor_sync(0xffffffffu, a0, off);
        a1 += __shfl_xor_sync(0xffffffffu, a1, off);
    }
    if (lane == 0) {
        float b = bada[l * 6 * D_ + j];
        g_mod[((size_t)l * B_ + 0) * 6 * D_ + j] = a0 + b;
        g_mod[((size_t)l * B_ + 1) * 6 * D_ + j] = a1 + b;
    }
}

// ---------------- LayerNorm + adaLN modulation ----------------
// one block (256 thr) per token row
__global__ void ln_mod_kernel(const float* __restrict__ x,
                              const float* __restrict__ mod,   // [B][6D] for this layer
                              int shOff, int scOff,
                              float* __restrict__ out) {
    int m = blockIdx.x, tid = threadIdx.x;
    const float4* row = reinterpret_cast<const float4*>(x + (size_t)m * D_);
    float4 v = row[tid];
    float s  = v.x + v.y + v.z + v.w;
    float sq = v.x*v.x + v.y*v.y + v.z*v.z + v.w*v.w;
    __shared__ float rs[8], rq[8];
    #pragma unroll
    for (int off = 16; off; off >>= 1) {
        s  += __shfl_xor_sync(0xffffffffu, s,  off);
        sq += __shfl_xor_sync(0xffffffffu, sq, off);
    }
    int lane = tid & 31, wid = tid >> 5;
    if (lane == 0) { rs[wid] = s; rq[wid] = sq; }
    __syncthreads();
    float ts = 0.f, tq = 0.f;
    #pragma unroll
    for (int i = 0; i < 8; i++) { ts += rs[i]; tq += rq[i]; }
    float mean = ts * (1.f / D_);
    float var  = tq * (1.f / D_) - mean * mean;
    float rstd = rsqrtf(var + 1e-6f);
    int b = m & 1;
    const float4* scp = reinterpret_cast<const float4*>(mod + (size_t)b * 6 * D_ + scOff);
    const float4* shp = reinterpret_cast<const float4*>(mod + (size_t)b * 6 * D_ + shOff);
    float4 sc = scp[tid], sh = shp[tid];
    float4 r;
    r.x = (v.x - mean) * rstd * (1.f + sc.x) + sh.x;
    r.y = (v.y - mean) * rstd * (1.f + sc.y) + sh.y;
    r.z = (v.z - mean) * rstd * (1.f + sc.z) + sh.z;
    r.w = (v.w - mean) * rstd * (1.f + sc.w) + sh.w;
    reinterpret_cast<float4*>(out + (size_t)m * D_)[tid] = r;
}

// ---------------- tf32 GEMM: C[M,N] = A[M,K] @ Bw[N,K]^T (+ epilogue) ----------------
// mode 0: C = acc + bias
// mode 1: C = relu(acc + bias)
// mode 2: C = xin + gate[b, gateOff+col] * (acc + bias)     (gated residual)
__device__ __forceinline__ uint32_t f2tf(float f) {
    uint32_t u; asm("cvt.rna.tf32.f32 %0, %1;" : "=r"(u) : "f"(f)); return u;
}

__global__ __launch_bounds__(256) void gemm_tf32(
    const float* __restrict__ A, const float* __restrict__ Bw,
    const float* __restrict__ bias, float* __restrict__ C,
    const float* __restrict__ xin, const float* __restrict__ mod, int gateOff,
    int M, int N, int K, int mode)
{
    __shared__ float As[2][128 * 20];
    __shared__ float Bs[2][128 * 20];
    int tid  = threadIdx.x;
    int lane = tid & 31, wid = tid >> 5;
    int warpM = wid & 3;        // 4 warps along M (32 rows each)
    int warpN = wid >> 2;       // 2 warps along N (64 cols each)
    int g = lane >> 2, q = lane & 3;
    int bm = blockIdx.y * 128, bn = blockIdx.x * 128;

    int lr = tid >> 2;          // 0..63
    int lc = (tid & 3) * 4;     // 0,4,8,12
    const float* Ag = A  + (size_t)(bm + lr) * K + lc;
    const float* Bg = Bw + (size_t)(bn + lr) * K + lc;

    float acc[2][8][4];
    #pragma unroll
    for (int i = 0; i < 2; i++)
        #pragma unroll
        for (int j = 0; j < 8; j++)
            #pragma unroll
            for (int k = 0; k < 4; k++) acc[i][j][k] = 0.f;

    // preload tile 0
    {
        float4 a0 = *(const float4*)Ag;
        float4 a1 = *(const float4*)(Ag + (size_t)64 * K);
        float4 b0 = *(const float4*)Bg;
        float4 b1 = *(const float4*)(Bg + (size_t)64 * K);
        *(float4*)&As[0][lr * 20 + lc]        = a0;
        *(float4*)&As[0][(lr + 64) * 20 + lc] = a1;
        *(float4*)&Bs[0][lr * 20 + lc]        = b0;
        *(float4*)&Bs[0][(lr + 64) * 20 + lc] = b1;
    }
    __syncthreads();

    int T = K >> 4;
    for (int t = 0; t < T; ++t) {
        int cur = t & 1;
        float4 a0, a1, b0, b1;
        if (t + 1 < T) {
            const float* Ap = Ag + (t + 1) * 16;
            const float* Bp = Bg + (t + 1) * 16;
            a0 = *(const float4*)Ap; a1 = *(const float4*)(Ap + (size_t)64 * K);
            b0 = *(const float4*)Bp; b1 = *(const float4*)(Bp + (size_t)64 * K);
        }
        const float* as = As[cur];
        const float* bs = Bs[cur];
        #pragma unroll
        for (int kk = 0; kk < 16; kk += 8) {
            uint32_t af[2][4];
            #pragma unroll
            for (int mt = 0; mt < 2; ++mt) {
                int r = warpM * 32 + mt * 16 + g;
                af[mt][0] = f2tf(as[r * 20 + kk + q]);
                af[mt][1] = f2tf(as[(r + 8) * 20 + kk + q]);
                af[mt][2] = f2tf(as[r * 20 + kk + 4 + q]);
                af[mt][3] = f2tf(as[(r + 8) * 20 + kk + 4 + q]);
            }
            uint32_t bf[8][2];
            #pragma unroll
            for (int nt = 0; nt < 8; ++nt) {
                int cn = warpN * 64 + nt * 8 + g;
                bf[nt][0] = f2tf(bs[cn * 20 + kk + q]);
                bf[nt][1] = f2tf(bs[cn * 20 + kk + 4 + q]);
            }
            #pragma unroll
            for (int mt = 0; mt < 2; ++mt)
                #pragma unroll
                for (int nt = 0; nt < 8; ++nt)
                    asm volatile(
                        "mma.sync.aligned.m16n8k8.row.col.f32.tf32.tf32.f32 "
                        "{%0,%1,%2,%3}, {%4,%5,%6,%7}, {%8,%9}, {%0,%1,%2,%3};"
                        : "+f"(acc[mt][nt][0]), "+f"(acc[mt][nt][1]),
                          "+f"(acc[mt][nt][2]), "+f"(acc[mt][nt][3])
                        : "r"(af[mt][0]), "r"(af[mt][1]), "r"(af[mt][2]), "r"(af[mt][3]),
                          "r"(bf[nt][0]), "r"(bf[nt][1]));
        }
        if (t + 1 < T) {
            int nxt = cur ^ 1;
            *(float4*)&As[nxt][lr * 20 + lc]        = a0;
            *(float4*)&As[nxt][(lr + 64) * 20 + lc] = a1;
            *(float4*)&Bs[nxt][lr * 20 + lc]        = b0;
            *(float4*)&Bs[nxt][(lr + 64) * 20 + lc] = b1;
        }
        __syncthreads();
    }

    // epilogue
    #pragma unroll
    for (int mt = 0; mt < 2; ++mt) {
        #pragma unroll
        for (int nt = 0; nt < 8; ++nt) {
            #pragma unroll
            for (int i = 0; i < 4; ++i) {
                int row = bm + warpM * 32 + mt * 16 + g + ((i >> 1) << 3);
                int col = bn + warpN * 64 + nt * 8 + q * 2 + (i & 1);
                float v = acc[mt][nt][i] + bias[col];
                if (mode == 1) v = fmaxf(v, 0.f);
                if (mode == 2) {
                    float gt = mod[(size_t)(row & 1) * 6 * D_ + gateOff + col];
                    v = xin[(size_t)row * N + col] + gt * v;
                }
                C[(size_t)row * N + col] = v;
            }
        }
    }
}

// ---------------- windowed attention (flash-style online softmax) ----------------
// grid (S/16, B*H), 512 threads; warp w handles query s0+w; K/V staged in smem chunks
__global__ __launch_bounds__(512) void attn_kernel(const float* __restrict__ qkv,
                                                   float* __restrict__ o) {
    __shared__ float Ks[32][64];
    __shared__ float Vs[32][64];
    int tid  = threadIdx.x;
    int lane = tid & 31, w = tid >> 5;
    int bh = blockIdx.y;
    int b = bh / H_, h = bh % H_;
    int s0 = blockIdx.x * 16;
    int s  = s0 + w;

    const float* qptr = qkv + ((size_t)(s * B_ + b)) * (3 * D_) + h * DH_;
    float q0 = qptr[lane], q1 = qptr[lane + 32];

    float mx = -1e30f, lsum = 0.f, o0 = 0.f, o1 = 0.f;

    int tlo = s0 - WIN_;       if (tlo < 0) tlo = 0;
    int thi = s0 + 15 + WIN_;  if (thi > S_ - 1) thi = S_ - 1;

    int jload = tid >> 6;      // 0..7
    int dload = tid & 63;

    for (int tb = tlo; tb <= thi; tb += 32) {
        int nk = thi - tb + 1; if (nk > 32) nk = 32;
        __syncthreads();
        for (int jj = jload; jj < nk; jj += 8) {
            int t = tb + jj;
            const float* kp = qkv + ((size_t)(t * B_ + b)) * (3 * D_) + D_ + h * DH_;
            Ks[jj][dload] = kp[dload];
            Vs[jj][dload] = kp[D_ + dload];
        }
        __syncthreads();
        for (int jj = 0; jj < nk; jj++) {
            int t = tb + jj;
            int dist = t - s; if (dist < 0) dist = -dist;
            if (dist <= WIN_) {
                float dp = q0 * Ks[jj][lane] + q1 * Ks[jj][lane + 32];
                #pragma unroll
                for (int off = 16; off; off >>= 1)
                    dp += __shfl_xor_sync(0xffffffffu, dp, off);
                float sc = dp * 0.125f;                 // 1/sqrt(64)
                float mnew = fmaxf(mx, sc);
                float corr = expf(mx - mnew);
                float p    = expf(sc - mnew);
                lsum = lsum * corr + p;
                o0 = o0 * corr + p * Vs[jj][lane];
                o1 = o1 * corr + p * Vs[jj][lane + 32];
                mx = mnew;
            }
        }
    }
    float inv = 1.f / lsum;
    float* op = o + ((size_t)(s * B_ + b)) * D_ + h * DH_;
    op[lane]      = o0 * inv;
    op[lane + 32] = o1 * inv;
}

// ---------------- launcher ----------------
extern "C" void kernel_launch(void* const* d_in, const int* in_sizes, int n_in,
                              void* d_out, int out_size) {
    const float* x_in   = (const float*)d_in[0];
    const float* c      = (const float*)d_in[1];
    const float* w_qkv  = (const float*)d_in[2];
    const float* b_qkv  = (const float*)d_in[3];
    const float* w_out  = (const float*)d_in[4];
    const float* b_out  = (const float*)d_in[5];
    const float* w_mlp1 = (const float*)d_in[6];
    const float* b_mlp1 = (const float*)d_in[7];
    const float* w_mlp2 = (const float*)d_in[8];
    const float* b_mlp2 = (const float*)d_in[9];
    const float* w_ada  = (const float*)d_in[10];
    const float* b_ada  = (const float*)d_in[11];
    float* x = (float*)d_out;

    float *mod, *xm, *qkv, *o, *h;
    cudaGetSymbolAddress((void**)&mod, g_mod);
    cudaGetSymbolAddress((void**)&xm,  g_xm);
    cudaGetSymbolAddress((void**)&qkv, g_qkv);
    cudaGetSymbolAddress((void**)&o,   g_o);
    cudaGetSymbolAddress((void**)&h,   g_h);

    cudaMemcpyAsync(x, x_in, (size_t)M_ * D_ * sizeof(float), cudaMemcpyDeviceToDevice);

    mod_kernel<<<(L_ * 6 * D_) / 8, 256>>>(c, w_ada, b_ada);

    for (int l = 0; l < L_; l++) {
        const float* modl = mod + (size_t)l * B_ * 6 * D_;
        // --- attention branch ---
        ln_mod_kernel<<<M_, 256>>>(x, modl, 0 /*sh_msa*/, D_ /*sc_msa*/, xm);
        gemm_tf32<<<dim3(3 * D_ / 128, M_ / 128), 256>>>(
            xm, w_qkv + (size_t)l * 3 * D_ * D_, b_qkv + (size_t)l * 3 * D_,
            qkv, nullptr, nullptr, 0, M_, 3 * D_, D_, 0);
        attn_kernel<<<dim3(S_ / 16, B_ * H_), 512>>>(qkv, o);
        gemm_tf32<<<dim3(D_ / 128, M_ / 128), 256>>>(
            o, w_out + (size_t)l * D_ * D_, b_out + (size_t)l * D_,
            x, x, modl, 2 * D_ /*g_msa*/, M_, D_, D_, 2);
        // --- MLP branch ---
        ln_mod_kernel<<<M_, 256>>>(x, modl, 3 * D_ /*sh_mlp*/, 4 * D_ /*sc_mlp*/, xm);
        gemm_tf32<<<dim3(4 * D_ / 128, M_ / 128), 256>>>(
            xm, w_mlp1 + (size_t)l * 4 * D_ * D_, b_mlp1 + (size_t)l * 4 * D_,
            h, nullptr, nullptr, 0, M_, 4 * D_, D_, 1);
        gemm_tf32<<<dim3(D_ / 128, M_ / 128), 256>>>(
            h, w_mlp2 + (size_t)l * D_ * 4 * D_, b_mlp2 + (size_t)l * D_,
            x, x, modl, 5 * D_ /*g_mlp*/, M_, D_, 4 * D_, 2);
    }
}

// round 4
// speedup vs baseline: 1.3535x; 1.3535x over previous
#include <cuda_runtime.h>
#include <cstdint>

#define S_   1024
#define B_   2
#define D_   1024
#define H_   16
#define DH_  64
#define L_   4
#define WIN_ 64
#define M_   (S_*B_)   // 2048 token rows

// ---------------- scratch (no allocations allowed) ----------------
__device__ float g_mod[L_*B_*6*D_];
__device__ float g_xm [M_*D_];
__device__ float g_qkv[M_*3*D_];
__device__ float g_o  [M_*D_];
__device__ float g_h  [M_*4*D_];
// tf32-rounded weight copies
__device__ float g_wqkv [L_*3*D_*D_];
__device__ float g_wout [L_*D_*D_];
__device__ float g_wmlp1[L_*4*D_*D_];
__device__ float g_wmlp2[L_*D_*4*D_];

__device__ __forceinline__ uint32_t f2tf(float f) {
    uint32_t u; asm("cvt.rna.tf32.f32 %0, %1;" : "=r"(u) : "f"(f)); return u;
}
__device__ __forceinline__ uint32_t smem_u32(const void* p) {
    uint32_t a; asm("{ .reg .u64 t; cvta.to.shared.u64 t, %1; cvt.u32.u64 %0, t; }" : "=r"(a) : "l"(p));
    return a;
}
#define CP_ASYNC16(dst, src) \
    asm volatile("cp.async.cg.shared.global [%0], [%1], 16;" :: "r"(dst), "l"(src))

// ---------------- weight pre-round to tf32 (RNA) ----------------
__global__ void round_kernel(const float* __restrict__ src, float* __restrict__ dst, int n4) {
    int i = blockIdx.x * blockDim.x + threadIdx.x;
    if (i < n4) {
        float4 v = reinterpret_cast<const float4*>(src)[i];
        v.x = __uint_as_float(f2tf(v.x));
        v.y = __uint_as_float(f2tf(v.y));
        v.z = __uint_as_float(f2tf(v.z));
        v.w = __uint_as_float(f2tf(v.w));
        reinterpret_cast<float4*>(dst)[i] = v;
    }
}

// ---------------- adaLN modulation ----------------
__global__ void mod_kernel(const float* __restrict__ c,
                           const float* __restrict__ wada,
                           const float* __restrict__ bada) {
    int tid = threadIdx.x, lane = tid & 31;
    int widx = blockIdx.x * 8 + (tid >> 5);
    int l = widx / (6 * D_), j = widx % (6 * D_);
    const float* wr = wada + ((size_t)l * 6 * D_ + j) * D_;
    float a0 = 0.f, a1 = 0.f;
    for (int k = lane; k < D_; k += 32) {
        float wv = wr[k];
        a0 += wv * fmaxf(c[k], 0.f);
        a1 += wv * fmaxf(c[D_ + k], 0.f);
    }
    #pragma unroll
    for (int off = 16; off; off >>= 1) {
        a0 += __shfl_xor_sync(0xffffffffu, a0, off);
        a1 += __shfl_xor_sync(0xffffffffu, a1, off);
    }
    if (lane == 0) {
        float b = bada[l * 6 * D_ + j];
        g_mod[((size_t)l * B_ + 0) * 6 * D_ + j] = a0 + b;
        g_mod[((size_t)l * B_ + 1) * 6 * D_ + j] = a1 + b;
    }
}

// ---------------- LayerNorm + adaLN modulate (tf32-rounded output) ----------------
__global__ void ln_mod_kernel(const float* __restrict__ x,
                              const float* __restrict__ mod,
                              int shOff, int scOff,
                              float* __restrict__ out) {
    int m = blockIdx.x, tid = threadIdx.x;
    const float4* row = reinterpret_cast<const float4*>(x + (size_t)m * D_);
    float4 v = row[tid];
    float s  = v.x + v.y + v.z + v.w;
    float sq = v.x*v.x + v.y*v.y + v.z*v.z + v.w*v.w;
    __shared__ float rs[8], rq[8];
    #pragma unroll
    for (int off = 16; off; off >>= 1) {
        s  += __shfl_xor_sync(0xffffffffu, s,  off);
        sq += __shfl_xor_sync(0xffffffffu, sq, off);
    }
    int lane = tid & 31, wid = tid >> 5;
    if (lane == 0) { rs[wid] = s; rq[wid] = sq; }
    __syncthreads();
    float ts = 0.f, tq = 0.f;
    #pragma unroll
    for (int i = 0; i < 8; i++) { ts += rs[i]; tq += rq[i]; }
    float mean = ts * (1.f / D_);
    float var  = tq * (1.f / D_) - mean * mean;
    float rstd = rsqrtf(var + 1e-6f);
    int b = m & 1;
    const float4* scp = reinterpret_cast<const float4*>(mod + (size_t)b * 6 * D_ + scOff);
    const float4* shp = reinterpret_cast<const float4*>(mod + (size_t)b * 6 * D_ + shOff);
    float4 sc = scp[tid], sh = shp[tid];
    float4 r;
    r.x = __uint_as_float(f2tf((v.x - mean) * rstd * (1.f + sc.x) + sh.x));
    r.y = __uint_as_float(f2tf((v.y - mean) * rstd * (1.f + sc.y) + sh.y));
    r.z = __uint_as_float(f2tf((v.z - mean) * rstd * (1.f + sc.z) + sh.z));
    r.w = __uint_as_float(f2tf((v.w - mean) * rstd * (1.f + sc.w) + sh.w));
    reinterpret_cast<float4*>(out + (size_t)m * D_)[tid] = r;
}

// ---------------- mma.sync tf32 GEMM, 3-stage cp.async pipeline ----------------
// CTA tile 128x128, K-stage 32. 8 warps: 2(M) x 4(N), warp tile 64x32.
// Inputs A, W are ALREADY tf32-rounded fp32.
// mode 0: C = acc + bias
// mode 1: C = round_tf32(relu(acc + bias))
// mode 2: C = xin + gate * (acc + bias)
#define PAD 36
#define STAGE_FLOATS (128*PAD)            // 4608 floats per matrix per stage
#define STAGE_BYTES  (STAGE_FLOATS*4)     // 18432
#define STAGE_TOTAL  (2*STAGE_BYTES)      // 36864 (A + B)
#define NSTAGES 3

__global__ __launch_bounds__(256, 2)
void gemm_tc(const float* __restrict__ A, const float* __restrict__ W,
             const float* __restrict__ bias, float* __restrict__ C,
             const float* __restrict__ xin, const float* __restrict__ mod, int gateOff,
             int N, int K, int mode)
{
    extern __shared__ float sm[];
    uint32_t sbase = smem_u32(sm);
    int tid = threadIdx.x, lane = tid & 31, w = tid >> 5;
    int warpM = w >> 2, warpN = w & 3;        // 2 x 4
    int g = lane >> 2, q = lane & 3;
    int bm = blockIdx.y * 128, bn = blockIdx.x * 128;

    // stage loader: A 128x32 + B 128x32 floats, 16B cp.async, pitch 144B
    auto loadStage = [&](int slot, int kidx) {
        int k0 = kidx << 5;
        uint32_t aB = sbase + slot * STAGE_TOTAL;
        #pragma unroll
        for (int i = 0; i < 4; i++) {
            int seg = tid + i * 256;
            int row = seg >> 3, c = seg & 7;
            CP_ASYNC16(aB + row * (PAD*4) + c * 16,
                       A + (size_t)(bm + row) * K + k0 + c * 4);
        }
        #pragma unroll
        for (int i = 0; i < 4; i++) {
            int seg = tid + i * 256;
            int row = seg >> 3, c = seg & 7;
            CP_ASYNC16(aB + STAGE_BYTES + row * (PAD*4) + c * 16,
                       W + (size_t)(bn + row) * K + k0 + c * 4);
        }
        asm volatile("cp.async.commit_group;");
    };

    float acc[4][4][4];
    #pragma unroll
    for (int i = 0; i < 4; i++)
        #pragma unroll
        for (int j = 0; j < 4; j++)
            #pragma unroll
            for (int k = 0; k < 4; k++) acc[i][j][k] = 0.f;

    const int T = K >> 5;
    loadStage(0, 0);
    loadStage(1, 1);

    for (int t = 0; t < T; t++) {
        if (t < T - 1) asm volatile("cp.async.wait_group 1;");
        else           asm volatile("cp.async.wait_group 0;");
        __syncthreads();
        if (t + 2 < T) loadStage((t + 2) % NSTAGES, t + 2);

        const float* as = sm + (t % NSTAGES) * (STAGE_TOTAL / 4);
        const float* bs = as + STAGE_FLOATS;
        int arow0 = warpM * 64 + g;
        int brow0 = warpN * 32 + g;
        #pragma unroll
        for (int kk = 0; kk < 32; kk += 8) {
            uint32_t af[4][4], bf[4][2];
            #pragma unroll
            for (int mt = 0; mt < 4; mt++) {
                int r = arow0 + mt * 16;
                af[mt][0] = __float_as_uint(as[r * PAD + kk + q]);
                af[mt][1] = __float_as_uint(as[(r + 8) * PAD + kk + q]);
                af[mt][2] = __float_as_uint(as[r * PAD + kk + q + 4]);
                af[mt][3] = __float_as_uint(as[(r + 8) * PAD + kk + q + 4]);
            }
            #pragma unroll
            for (int nt = 0; nt < 4; nt++) {
                int cn = brow0 + nt * 8;
                bf[nt][0] = __float_as_uint(bs[cn * PAD + kk + q]);
                bf[nt][1] = __float_as_uint(bs[cn * PAD + kk + q + 4]);
            }
            #pragma unroll
            for (int mt = 0; mt < 4; mt++)
                #pragma unroll
                for (int nt = 0; nt < 4; nt++)
                    asm volatile(
                        "mma.sync.aligned.m16n8k8.row.col.f32.tf32.tf32.f32 "
                        "{%0,%1,%2,%3}, {%4,%5,%6,%7}, {%8,%9}, {%0,%1,%2,%3};"
                        : "+f"(acc[mt][nt][0]), "+f"(acc[mt][nt][1]),
                          "+f"(acc[mt][nt][2]), "+f"(acc[mt][nt][3])
                        : "r"(af[mt][0]), "r"(af[mt][1]), "r"(af[mt][2]), "r"(af[mt][3]),
                          "r"(bf[nt][0]), "r"(bf[nt][1]));
        }
    }

    // epilogue
    float bz[4][2], gz[2][4][2];
    #pragma unroll
    for (int nt = 0; nt < 4; nt++) {
        int col = bn + warpN * 32 + nt * 8 + q * 2;
        bz[nt][0] = bias[col];
        bz[nt][1] = bias[col + 1];
        if (mode == 2) {
            gz[0][nt][0] = mod[gateOff + col];
            gz[0][nt][1] = mod[gateOff + col + 1];
            gz[1][nt][0] = mod[6 * D_ + gateOff + col];
            gz[1][nt][1] = mod[6 * D_ + gateOff + col + 1];
        }
    }
    #pragma unroll
    for (int mt = 0; mt < 4; mt++) {
        #pragma unroll
        for (int half = 0; half < 2; half++) {
            int r = warpM * 64 + mt * 16 + g + half * 8;
            size_t rowoff = (size_t)(bm + r) * N;
            int par = r & 1;
            #pragma unroll
            for (int nt = 0; nt < 4; nt++) {
                int col = bn + warpN * 32 + nt * 8 + q * 2;
                float v0 = acc[mt][nt][half * 2 + 0] + bz[nt][0];
                float v1 = acc[mt][nt][half * 2 + 1] + bz[nt][1];
                if (mode == 1) {
                    v0 = __uint_as_float(f2tf(fmaxf(v0, 0.f)));
                    v1 = __uint_as_float(f2tf(fmaxf(v1, 0.f)));
                } else if (mode == 2) {
                    float2 xi = *reinterpret_cast<const float2*>(xin + rowoff + col);
                    v0 = xi.x + gz[par][nt][0] * v0;
                    v1 = xi.y + gz[par][nt][1] * v1;
                }
                float2 r2; r2.x = v0; r2.y = v1;
                *reinterpret_cast<float2*>(C + rowoff + col) = r2;
            }
        }
    }
}

// ---------------- windowed attention (flash-style, 4-key groups) ----------------
__global__ __launch_bounds__(512) void attn_kernel(const float* __restrict__ qkv,
                                                   float* __restrict__ o) {
    __shared__ float Ks[32][64];
    __shared__ float Vs[32][64];
    int tid = threadIdx.x, lane = tid & 31, w = tid >> 5;
    int bh = blockIdx.y;
    int b = bh / H_, h = bh % H_;
    int s0 = blockIdx.x * 16;
    int s  = s0 + w;

    const float* qptr = qkv + ((size_t)(s * B_ + b)) * (3 * D_) + h * DH_;
    float q0 = qptr[lane], q1 = qptr[lane + 32];

    float mx = 0.f, lsum = 0.f, o0 = 0.f, o1 = 0.f;
    int tlo = s0 - WIN_;       if (tlo < 0) tlo = 0;
    int thi = s0 + 15 + WIN_;  if (thi > S_ - 1) thi = S_ - 1;
    int jload = tid >> 6, dload = tid & 63;

    for (int tb = tlo; tb <= thi; tb += 32) {
        __syncthreads();
        for (int jj = jload; jj < 32; jj += 8) {
            int t = tb + jj; if (t > thi) t = thi;       // clamp (masked later)
            const float* kp = qkv + ((size_t)(t * B_ + b)) * (3 * D_) + D_ + h * DH_;
            Ks[jj][dload] = kp[dload];
            Vs[jj][dload] = kp[D_ + dload];
        }
        __syncthreads();
        #pragma unroll
        for (int jj = 0; jj < 32; jj += 4) {
            float sc[4];
            #pragma unroll
            for (int i = 0; i < 4; i++) {
                int t = tb + jj + i;
                float dp = q0 * Ks[jj + i][lane] + q1 * Ks[jj + i][lane + 32];
                #pragma unroll
                for (int off = 16; off; off >>= 1)
                    dp += __shfl_xor_sync(0xffffffffu, dp, off);
                int dist = t - s; if (dist < 0) dist = -dist;
                sc[i] = (dist <= WIN_ && t <= thi) ? dp * 0.125f : -1e30f;
            }
            float mnew = fmaxf(fmaxf(fmaxf(sc[0], sc[1]), fmaxf(sc[2], sc[3])), mx);
            float corr = __expf(mx - mnew);
            float p0 = __expf(sc[0] - mnew);
            float p1 = __expf(sc[1] - mnew);
            float p2 = __expf(sc[2] - mnew);
            float p3 = __expf(sc[3] - mnew);
            lsum = lsum * corr + ((p0 + p1) + (p2 + p3));
            o0 = o0 * corr + p0 * Vs[jj][lane]     + p1 * Vs[jj + 1][lane]
                           + p2 * Vs[jj + 2][lane] + p3 * Vs[jj + 3][lane];
            o1 = o1 * corr + p0 * Vs[jj][lane + 32]     + p1 * Vs[jj + 1][lane + 32]
                           + p2 * Vs[jj + 2][lane + 32] + p3 * Vs[jj + 3][lane + 32];
            mx = mnew;
        }
    }
    float inv = 1.f / lsum;
    float* op = o + ((size_t)(s * B_ + b)) * D_ + h * DH_;
    op[lane]      = __uint_as_float(f2tf(o0 * inv));
    op[lane + 32] = __uint_as_float(f2tf(o1 * inv));
}

// ---------------- launcher ----------------
extern "C" void kernel_launch(void* const* d_in, const int* in_sizes, int n_in,
                              void* d_out, int out_size) {
    const float* x_in   = (const float*)d_in[0];
    const float* c      = (const float*)d_in[1];
    const float* w_qkv  = (const float*)d_in[2];
    const float* b_qkv  = (const float*)d_in[3];
    const float* w_out  = (const float*)d_in[4];
    const float* b_out  = (const float*)d_in[5];
    const float* w_mlp1 = (const float*)d_in[6];
    const float* b_mlp1 = (const float*)d_in[7];
    const float* w_mlp2 = (const float*)d_in[8];
    const float* b_mlp2 = (const float*)d_in[9];
    const float* w_ada  = (const float*)d_in[10];
    const float* b_ada  = (const float*)d_in[11];
    float* x = (float*)d_out;

    float *mod, *xm, *qkv, *o, *h, *wq, *wo, *w1, *w2;
    cudaGetSymbolAddress((void**)&mod, g_mod);
    cudaGetSymbolAddress((void**)&xm,  g_xm);
    cudaGetSymbolAddress((void**)&qkv, g_qkv);
    cudaGetSymbolAddress((void**)&o,   g_o);
    cudaGetSymbolAddress((void**)&h,   g_h);
    cudaGetSymbolAddress((void**)&wq,  g_wqkv);
    cudaGetSymbolAddress((void**)&wo,  g_wout);
    cudaGetSymbolAddress((void**)&w1,  g_wmlp1);
    cudaGetSymbolAddress((void**)&w2,  g_wmlp2);

    const int gsmem = NSTAGES * STAGE_TOTAL;   // 110592 B
    cudaFuncSetAttribute(gemm_tc, cudaFuncAttributeMaxDynamicSharedMemorySize, gsmem);

    cudaMemcpyAsync(x, x_in, (size_t)M_ * D_ * sizeof(float), cudaMemcpyDeviceToDevice);

    // weight pre-round (RNA -> tf32)
    {
        int n;
        n = L_*3*D_*D_/4;  round_kernel<<<(n+255)/256, 256>>>(w_qkv,  wq, n);
        n = L_*D_*D_/4;    round_kernel<<<(n+255)/256, 256>>>(w_out,  wo, n);
        n = L_*4*D_*D_/4;  round_kernel<<<(n+255)/256, 256>>>(w_mlp1, w1, n);
        n = L_*D_*4*D_/4;  round_kernel<<<(n+255)/256, 256>>>(w_mlp2, w2, n);
    }

    mod_kernel<<<(L_ * 6 * D_) / 8, 256>>>(c, w_ada, b_ada);

    for (int l = 0; l < L_; l++) {
        const float* modl = mod + (size_t)l * B_ * 6 * D_;
        // --- attention branch ---
        ln_mod_kernel<<<M_, 256>>>(x, modl, 0, D_, xm);
        gemm_tc<<<dim3(3 * D_ / 128, M_ / 128), 256, gsmem>>>(
            xm, wq + (size_t)l * 3 * D_ * D_, b_qkv + (size_t)l * 3 * D_,
            qkv, nullptr, nullptr, 0, 3 * D_, D_, 0);
        attn_kernel<<<dim3(S_ / 16, B_ * H_), 512>>>(qkv, o);
        gemm_tc<<<dim3(D_ / 128, M_ / 128), 256, gsmem>>>(
            o, wo + (size_t)l * D_ * D_, b_out + (size_t)l * D_,
            x, x, modl, 2 * D_, D_, D_, 2);
        // --- MLP branch ---
        ln_mod_kernel<<<M_, 256>>>(x, modl, 3 * D_, 4 * D_, xm);
        gemm_tc<<<dim3(4 * D_ / 128, M_ / 128), 256, gsmem>>>(
            xm, w1 + (size_t)l * 4 * D_ * D_, b_mlp1 + (size_t)l * 4 * D_,
            h, nullptr, nullptr, 0, 4 * D_, D_, 1);
        gemm_tc<<<dim3(D_ / 128, M_ / 128), 256, gsmem>>>(
            h, w2 + (size_t)l * D_ * 4 * D_, b_mlp2 + (size_t)l * D_,
            x, x, modl, 5 * D_, D_, 4 * D_, 2);
    }
}

// round 6
// speedup vs baseline: 1.9134x; 1.4137x over previous
#include <cuda_runtime.h>
#include <cuda_fp16.h>
#include <cstdint>

#define S_   1024
#define B_   2
#define D_   1024
#define H_   16
#define DH_  64
#define L_   4
#define WIN_ 64
#define M_   (S_*B_)   // 2048 token rows

// ---------------- scratch (no allocations allowed) ----------------
__device__ float  g_mod[L_*B_*6*D_];
__device__ __half g_xm [M_*D_];        // LN-modulated activations (fp16)
__device__ float  g_qkv[M_*3*D_];      // qkv projections (fp32 for attention)
__device__ __half g_o  [M_*D_];        // attention output (fp16)
__device__ __half g_h  [M_*4*D_];      // MLP hidden (fp16)
// fp16 weight copies
__device__ __half g_wqkv [L_*3*D_*D_];
__device__ __half g_wout [L_*D_*D_];
__device__ __half g_wmlp1[L_*4*D_*D_];
__device__ __half g_wmlp2[L_*D_*4*D_];

__device__ __forceinline__ uint32_t smem_u32(const void* p) {
    uint32_t a; asm("{ .reg .u64 t; cvta.to.shared.u64 t, %1; cvt.u32.u64 %0, t; }" : "=r"(a) : "l"(p));
    return a;
}
__device__ __forceinline__ uint32_t h2u(__half2 h) {
    return *reinterpret_cast<uint32_t*>(&h);
}
#define CP_ASYNC16(dst, src) \
    asm volatile("cp.async.cg.shared.global [%0], [%1], 16;" :: "r"(dst), "l"(src))
#define LDSM4(r0, r1, r2, r3, addr) \
    asm volatile("ldmatrix.sync.aligned.m8n8.x4.shared.b16 {%0,%1,%2,%3}, [%4];" \
        : "=r"(r0), "=r"(r1), "=r"(r2), "=r"(r3) : "r"(addr))

// ---------------- weight convert fp32 -> fp16 ----------------
__global__ void cvt_kernel(const float* __restrict__ src, __half* __restrict__ dst, int n8) {
    int i = blockIdx.x * blockDim.x + threadIdx.x;
    if (i < n8) {
        float4 v0 = reinterpret_cast<const float4*>(src)[2*i];
        float4 v1 = reinterpret_cast<const float4*>(src)[2*i+1];
        uint4 u;
        u.x = h2u(__floats2half2_rn(v0.x, v0.y));
        u.y = h2u(__floats2half2_rn(v0.z, v0.w));
        u.z = h2u(__floats2half2_rn(v1.x, v1.y));
        u.w = h2u(__floats2half2_rn(v1.z, v1.w));
        reinterpret_cast<uint4*>(dst)[i] = u;
    }
}

// ---------------- adaLN modulation ----------------
__global__ void mod_kernel(const float* __restrict__ c,
                           const float* __restrict__ wada,
                           const float* __restrict__ bada) {
    int tid = threadIdx.x, lane = tid & 31;
    int widx = blockIdx.x * 8 + (tid >> 5);
    int l = widx / (6 * D_), j = widx % (6 * D_);
    const float* wr = wada + ((size_t)l * 6 * D_ + j) * D_;
    float a0 = 0.f, a1 = 0.f;
    for (int k = lane; k < D_; k += 32) {
        float wv = wr[k];
        a0 += wv * fmaxf(c[k], 0.f);
        a1 += wv * fmaxf(c[D_ + k], 0.f);
    }
    #pragma unroll
    for (int off = 16; off; off >>= 1) {
        a0 += __shfl_xor_sync(0xffffffffu, a0, off);
        a1 += __shfl_xor_sync(0xffffffffu, a1, off);
    }
    if (lane == 0) {
        float b = bada[l * 6 * D_ + j];
        g_mod[((size_t)l * B_ + 0) * 6 * D_ + j] = a0 + b;
        g_mod[((size_t)l * B_ + 1) * 6 * D_ + j] = a1 + b;
    }
}

// ---------------- LayerNorm + adaLN modulate -> fp16 ----------------
__global__ void ln_mod_kernel(const float* __restrict__ x,
                              const float* __restrict__ mod,
                              int shOff, int scOff,
                              __half* __restrict__ out) {
    int m = blockIdx.x, tid = threadIdx.x;
    const float4* row = reinterpret_cast<const float4*>(x + (size_t)m * D_);
    float4 v = row[tid];
    float s  = v.x + v.y + v.z + v.w;
    float sq = v.x*v.x + v.y*v.y + v.z*v.z + v.w*v.w;
    __shared__ float rs[8], rq[8];
    #pragma unroll
    for (int off = 16; off; off >>= 1) {
        s  += __shfl_xor_sync(0xffffffffu, s,  off);
        sq += __shfl_xor_sync(0xffffffffu, sq, off);
    }
    int lane = tid & 31, wid = tid >> 5;
    if (lane == 0) { rs[wid] = s; rq[wid] = sq; }
    __syncthreads();
    float ts = 0.f, tq = 0.f;
    #pragma unroll
    for (int i = 0; i < 8; i++) { ts += rs[i]; tq += rq[i]; }
    float mean = ts * (1.f / D_);
    float var  = tq * (1.f / D_) - mean * mean;
    float rstd = rsqrtf(var + 1e-6f);
    int b = m & 1;
    const float4* scp = reinterpret_cast<const float4*>(mod + (size_t)b * 6 * D_ + scOff);
    const float4* shp = reinterpret_cast<const float4*>(mod + (size_t)b * 6 * D_ + shOff);
    float4 sc = scp[tid], sh = shp[tid];
    __half2 h0 = __floats2half2_rn((v.x - mean) * rstd * (1.f + sc.x) + sh.x,
                                   (v.y - mean) * rstd * (1.f + sc.y) + sh.y);
    __half2 h1 = __floats2half2_rn((v.z - mean) * rstd * (1.f + sc.z) + sh.z,
                                   (v.w - mean) * rstd * (1.f + sc.w) + sh.w);
    __half2* op = reinterpret_cast<__half2*>(out + (size_t)m * D_);
    op[tid * 2]     = h0;
    op[tid * 2 + 1] = h1;
}

// ---------------- fp16 GEMM: C[M,N] = A[M,K] @ W[N,K]^T (+ epilogue) ----------------
// CTA tile 128 x TN, K-stage 64, 3-stage cp.async. 8 warps: 2(M) x 4(N).
// mode 0: Cf = acc + bias                      (fp32 out)
// mode 1: Ch = half(relu(acc + bias))          (fp16 out)
// mode 2: Cf = xin + gate * (acc + bias)       (fp32 out, gated residual)
#define GP 72          // smem row pitch in halves (144 B)
template<int TN>
__global__ __launch_bounds__(256, 2)
void gemm_fp16(const __half* __restrict__ A, const __half* __restrict__ W,
               const float* __restrict__ bias,
               float* __restrict__ Cf, __half* __restrict__ Ch,
               const float* __restrict__ xin, const float* __restrict__ mod, int gateOff,
               int N, int K, int mode)
{
    constexpr int NT = TN / 32;                 // n8 frags per warp (4 or 2)
    constexpr int ABYTES = 128 * GP * 2;        // 18432
    constexpr int BBYTES = TN * GP * 2;
    constexpr int STG = ABYTES + BBYTES;
    extern __shared__ char smraw[];
    uint32_t sbase = smem_u32(smraw);
    int tid = threadIdx.x, lane = tid & 31, w = tid >> 5;
    int warpM = w >> 2, warpN = w & 3;          // 2 x 4
    int g = lane >> 2, q = lane & 3;
    int bm = blockIdx.y * 128, bn = blockIdx.x * TN;

    uint32_t aoff2 = 2u * (((lane & 7) + (lane & 8)) * GP + ((lane & 16) >> 1));
    uint32_t boff2 = 2u * (((lane & 7) + ((lane & 16) >> 1)) * GP + (lane & 8));

    auto loadStage = [&](int slot, int kidx) {
        int k0 = kidx << 6;
        uint32_t aB = sbase + slot * STG;
        #pragma unroll
        for (int i = 0; i < 4; i++) {
            int seg = tid + i * 256;
            int row = seg >> 3, c = seg & 7;
            CP_ASYNC16(aB + row * (GP*2) + c * 16,
                       A + (size_t)(bm + row) * K + k0 + c * 8);
        }
        #pragma unroll
        for (int i = 0; i < TN / 32; i++) {
            int seg = tid + i * 256;
            int row = seg >> 3, c = seg & 7;
            CP_ASYNC16(aB + ABYTES + row * (GP*2) + c * 16,
                       W + (size_t)(bn + row) * K + k0 + c * 8);
        }
        asm volatile("cp.async.commit_group;");
    };

    float acc[4][NT][4];
    #pragma unroll
    for (int i = 0; i < 4; i++)
        #pragma unroll
        for (int j = 0; j < NT; j++)
            #pragma unroll
            for (int k = 0; k < 4; k++) acc[i][j][k] = 0.f;

    const int T = K >> 6;
    loadStage(0, 0);
    loadStage(1, 1);

    for (int t = 0; t < T; t++) {
        if (t < T - 1) asm volatile("cp.async.wait_group 1;");
        else           asm volatile("cp.async.wait_group 0;");
        __syncthreads();
        if (t + 2 < T) loadStage((t + 2) % 3, t + 2);

        uint32_t aBase = sbase + (t % 3) * STG;
        uint32_t bBase = aBase + ABYTES;
        #pragma unroll
        for (int kk = 0; kk < 4; kk++) {
            uint32_t af[4][4];
            #pragma unroll
            for (int mt = 0; mt < 4; mt++) {
                uint32_t ad = aBase + 2u * ((warpM * 64 + mt * 16) * GP + kk * 16) + aoff2;
                LDSM4(af[mt][0], af[mt][1], af[mt][2], af[mt][3], ad);
            }
            uint32_t bf[NT][2];
            #pragma unroll
            for (int nb = 0; nb < NT / 2; nb++) {
                uint32_t bd = bBase + 2u * ((warpN * (TN/4) + nb * 16) * GP + kk * 16) + boff2;
                uint32_t r0, r1, r2, r3;
                LDSM4(r0, r1, r2, r3, bd);
                bf[2*nb][0] = r0;   bf[2*nb][1] = r1;
                bf[2*nb+1][0] = r2; bf[2*nb+1][1] = r3;
            }
            #pragma unroll
            for (int mt = 0; mt < 4; mt++)
                #pragma unroll
                for (int nt = 0; nt < NT; nt++)
                    asm volatile(
                        "mma.sync.aligned.m16n8k16.row.col.f32.f16.f16.f32 "
                        "{%0,%1,%2,%3}, {%4,%5,%6,%7}, {%8,%9}, {%0,%1,%2,%3};"
                        : "+f"(acc[mt][nt][0]), "+f"(acc[mt][nt][1]),
                          "+f"(acc[mt][nt][2]), "+f"(acc[mt][nt][3])
                        : "r"(af[mt][0]), "r"(af[mt][1]), "r"(af[mt][2]), "r"(af[mt][3]),
                          "r"(bf[nt][0]), "r"(bf[nt][1]));
        }
    }

    // epilogue
    float bz[NT][2], gz[2][NT][2];
    #pragma unroll
    for (int nt = 0; nt < NT; nt++) {
        int col = bn + warpN * (TN/4) + nt * 8 + q * 2;
        bz[nt][0] = bias[col];
        bz[nt][1] = bias[col + 1];
        if (mode == 2) {
            gz[0][nt][0] = mod[gateOff + col];
            gz[0][nt][1] = mod[gateOff + col + 1];
            gz[1][nt][0] = mod[6 * D_ + gateOff + col];
            gz[1][nt][1] = mod[6 * D_ + gateOff + col + 1];
        }
    }
    #pragma unroll
    for (int mt = 0; mt < 4; mt++) {
        #pragma unroll
        for (int half = 0; half < 2; half++) {
            int r = warpM * 64 + mt * 16 + g + half * 8;
            size_t rowoff = (size_t)(bm + r) * N;
            int par = r & 1;
            #pragma unroll
            for (int nt = 0; nt < NT; nt++) {
                int col = bn + warpN * (TN/4) + nt * 8 + q * 2;
                float v0 = acc[mt][nt][half * 2 + 0] + bz[nt][0];
                float v1 = acc[mt][nt][half * 2 + 1] + bz[nt][1];
                if (mode == 1) {
                    __half2 hv = __floats2half2_rn(fmaxf(v0, 0.f), fmaxf(v1, 0.f));
                    *reinterpret_cast<__half2*>(Ch + rowoff + col) = hv;
                } else if (mode == 2) {
                    float2 xi = *reinterpret_cast<const float2*>(xin + rowoff + col);
                    float2 r2;
                    r2.x = xi.x + gz[par][nt][0] * v0;
                    r2.y = xi.y + gz[par][nt][1] * v1;
                    *reinterpret_cast<float2*>(Cf + rowoff + col) = r2;
                } else {
                    float2 r2; r2.x = v0; r2.y = v1;
                    *reinterpret_cast<float2*>(Cf + rowoff + col) = r2;
                }
            }
        }
    }
}

// ---------------- windowed attention (flash-style, 4-key groups) ----------------
__global__ __launch_bounds__(512) void attn_kernel(const float* __restrict__ qkv,
                                                   __half* __restrict__ o) {
    __shared__ float Ks[32][64];
    __shared__ float Vs[32][64];
    int tid = threadIdx.x, lane = tid & 31, w = tid >> 5;
    int bh = blockIdx.y;
    int b = bh / H_, h = bh % H_;
    int s0 = blockIdx.x * 16;
    int s  = s0 + w;

    const float* qptr = qkv + ((size_t)(s * B_ + b)) * (3 * D_) + h * DH_;
    float q0 = qptr[lane], q1 = qptr[lane + 32];

    float mx = 0.f, lsum = 0.f, o0 = 0.f, o1 = 0.f;
    int tlo = s0 - WIN_;       if (tlo < 0) tlo = 0;
    int thi = s0 + 15 + WIN_;  if (thi > S_ - 1) thi = S_ - 1;
    int jload = tid >> 6, dload = tid & 63;

    for (int tb = tlo; tb <= thi; tb += 32) {
        __syncthreads();
        for (int jj = jload; jj < 32; jj += 8) {
            int t = tb + jj; if (t > thi) t = thi;
            const float* kp = qkv + ((size_t)(t * B_ + b)) * (3 * D_) + D_ + h * DH_;
            Ks[jj][dload] = kp[dload];
            Vs[jj][dload] = kp[D_ + dload];
        }
        __syncthreads();
        #pragma unroll
        for (int jj = 0; jj < 32; jj += 4) {
            float sc[4];
            #pragma unroll
            for (int i = 0; i < 4; i++) {
                int t = tb + jj + i;
                float dp = q0 * Ks[jj + i][lane] + q1 * Ks[jj + i][lane + 32];
                #pragma unroll
                for (int off = 16; off; off >>= 1)
                    dp += __shfl_xor_sync(0xffffffffu, dp, off);
                int dist = t - s; if (dist < 0) dist = -dist;
                sc[i] = (dist <= WIN_ && t <= thi) ? dp * 0.125f : -1e30f;
            }
            float mnew = fmaxf(fmaxf(fmaxf(sc[0], sc[1]), fmaxf(sc[2], sc[3])), mx);
            float corr = __expf(mx - mnew);
            float p0 = __expf(sc[0] - mnew);
            float p1 = __expf(sc[1] - mnew);
            float p2 = __expf(sc[2] - mnew);
            float p3 = __expf(sc[3] - mnew);
            lsum = lsum * corr + ((p0 + p1) + (p2 + p3));
            o0 = o0 * corr + p0 * Vs[jj][lane]     + p1 * Vs[jj + 1][lane]
                           + p2 * Vs[jj + 2][lane] + p3 * Vs[jj + 3][lane];
            o1 = o1 * corr + p0 * Vs[jj][lane + 32]     + p1 * Vs[jj + 1][lane + 32]
                           + p2 * Vs[jj + 2][lane + 32] + p3 * Vs[jj + 3][lane + 32];
            mx = mnew;
        }
    }
    float inv = 1.f / lsum;
    __half* op = o + ((size_t)(s * B_ + b)) * D_ + h * DH_;
    op[lane]      = __float2half_rn(o0 * inv);
    op[lane + 32] = __float2half_rn(o1 * inv);
}

// ---------------- launcher ----------------
extern "C" void kernel_launch(void* const* d_in, const int* in_sizes, int n_in,
                              void* d_out, int out_size) {
    const float* x_in   = (const float*)d_in[0];
    const float* c      = (const float*)d_in[1];
    const float* w_qkv  = (const float*)d_in[2];
    const float* b_qkv  = (const float*)d_in[3];
    const float* w_out  = (const float*)d_in[4];
    const float* b_out  = (const float*)d_in[5];
    const float* w_mlp1 = (const float*)d_in[6];
    const float* b_mlp1 = (const float*)d_in[7];
    const float* w_mlp2 = (const float*)d_in[8];
    const float* b_mlp2 = (const float*)d_in[9];
    const float* w_ada  = (const float*)d_in[10];
    const float* b_ada  = (const float*)d_in[11];
    float* x = (float*)d_out;

    float  *mod, *qkv;
    __half *xm, *o, *h, *wq, *wo, *w1, *w2;
    cudaGetSymbolAddress((void**)&mod, g_mod);
    cudaGetSymbolAddress((void**)&xm,  g_xm);
    cudaGetSymbolAddress((void**)&qkv, g_qkv);
    cudaGetSymbolAddress((void**)&o,   g_o);
    cudaGetSymbolAddress((void**)&h,   g_h);
    cudaGetSymbolAddress((void**)&wq,  g_wqkv);
    cudaGetSymbolAddress((void**)&wo,  g_wout);
    cudaGetSymbolAddress((void**)&w1,  g_wmlp1);
    cudaGetSymbolAddress((void**)&w2,  g_wmlp2);

    const int smem128 = 3 * (128 * GP * 2 + 128 * GP * 2);  // 110592
    const int smem64  = 3 * (128 * GP * 2 + 64  * GP * 2);  // 82944
    cudaFuncSetAttribute(gemm_fp16<128>, cudaFuncAttributeMaxDynamicSharedMemorySize, smem128);
    cudaFuncSetAttribute(gemm_fp16<64>,  cudaFuncAttributeMaxDynamicSharedMemorySize, smem64);

    cudaMemcpyAsync(x, x_in, (size_t)M_ * D_ * sizeof(float), cudaMemcpyDeviceToDevice);

    // weight convert fp32 -> fp16
    {
        int n;
        n = L_*3*D_*D_/8;  cvt_kernel<<<(n+255)/256, 256>>>(w_qkv,  wq, n);
        n = L_*D_*D_/8;    cvt_kernel<<<(n+255)/256, 256>>>(w_out,  wo, n);
        n = L_*4*D_*D_/8;  cvt_kernel<<<(n+255)/256, 256>>>(w_mlp1, w1, n);
        n = L_*D_*4*D_/8;  cvt_kernel<<<(n+255)/256, 256>>>(w_mlp2, w2, n);
    }

    mod_kernel<<<(L_ * 6 * D_) / 8, 256>>>(c, w_ada, b_ada);

    for (int l = 0; l < L_; l++) {
        const float* modl = mod + (size_t)l * B_ * 6 * D_;
        // --- attention branch ---
        ln_mod_kernel<<<M_, 256>>>(x, modl, 0, D_, xm);
        gemm_fp16<128><<<dim3(3 * D_ / 128, M_ / 128), 256, smem128>>>(
            xm, wq + (size_t)l * 3 * D_ * D_, b_qkv + (size_t)l * 3 * D_,
            qkv, nullptr, nullptr, nullptr, 0, 3 * D_, D_, 0);
        attn_kernel<<<dim3(S_ / 16, B_ * H_), 512>>>(qkv, o);
        gemm_fp16<64><<<dim3(D_ / 64, M_ / 128), 256, smem64>>>(
            o, wo + (size_t)l * D_ * D_, b_out + (size_t)l * D_,
            x, nullptr, x, modl, 2 * D_, D_, D_, 2);
        // --- MLP branch ---
        ln_mod_kernel<<<M_, 256>>>(x, modl, 3 * D_, 4 * D_, xm);
        gemm_fp16<128><<<dim3(4 * D_ / 128, M_ / 128), 256, smem128>>>(
            xm, w1 + (size_t)l * 4 * D_ * D_, b_mlp1 + (size_t)l * 4 * D_,
            nullptr, h, nullptr, nullptr, 0, 4 * D_, D_, 1);
        gemm_fp16<64><<<dim3(D_ / 64, M_ / 128), 256, smem64>>>(
            h, w2 + (size_t)l * D_ * 4 * D_, b_mlp2 + (size_t)l * D_,
            x, nullptr, x, modl, 5 * D_, D_, 4 * D_, 2);
    }
}